// round 3
// baseline (speedup 1.0000x reference)
#include <cuda_runtime.h>

#define NN 50000
#define NE 800000
#define CC 64

// Scratch (device globals: no allocation allowed in kernel_launch)
__device__ float  g_deg[NN];
__device__ float  g_w[NE];
__device__ float4 g_T1[NN * (CC / 4)];   // T1 = L_hat @ x
__device__ float4 g_P2[NN * (CC / 4)];   // P2 = L_hat @ T1

// ---------------------------------------------------------------------------
// Zero scratch buffers
// ---------------------------------------------------------------------------
__global__ void zero_kernel() {
    int i = blockIdx.x * blockDim.x + threadIdx.x;
    int stride = gridDim.x * blockDim.x;
    for (int j = i; j < NN; j += stride) g_deg[j] = 0.0f;
    const int total4 = NN * (CC / 4);
    float4 z = make_float4(0.f, 0.f, 0.f, 0.f);
    for (int j = i; j < total4; j += stride) {
        g_T1[j] = z;
        g_P2[j] = z;
    }
}

// ---------------------------------------------------------------------------
// deg[r] = sum of edge_weight over edges with row == r
// ---------------------------------------------------------------------------
__global__ void deg_kernel(const int* __restrict__ row, const float* __restrict__ ew) {
    int e = blockIdx.x * blockDim.x + threadIdx.x;
    if (e < NE) {
        atomicAdd(&g_deg[row[e]], ew[e]);
    }
}

// ---------------------------------------------------------------------------
// w[e] = -dis[row]*ew*dis[col],  dis = deg>0 ? rsqrt(deg) : 0
// ---------------------------------------------------------------------------
__global__ void weight_kernel(const int* __restrict__ row, const int* __restrict__ col,
                              const float* __restrict__ ew) {
    int e = blockIdx.x * blockDim.x + threadIdx.x;
    if (e < NE) {
        float dr = g_deg[row[e]];
        float dc = g_deg[col[e]];
        float ir = (dr > 0.0f) ? rsqrtf(dr) : 0.0f;
        float ic = (dc > 0.0f) ? rsqrtf(dc) : 0.0f;
        g_w[e] = -ir * ew[e] * ic;
    }
}

// ---------------------------------------------------------------------------
// Propagation: dst[row] += w[e] * src[col]   (16 threads per edge, float4 each)
// Vector RED (red.global.add.v4.f32) cuts atomic-issue count 4x vs scalar.
// ---------------------------------------------------------------------------
__device__ __forceinline__ void prop_body(long long idx,
                                          const int* __restrict__ row,
                                          const int* __restrict__ col,
                                          const float4* __restrict__ src,
                                          float* __restrict__ dst) {
    int e = (int)(idx >> 4);
    int j = (int)(idx & 15);
    float wv = __ldg(&g_w[e]);
    if (wv == 0.0f) return;
    int c = __ldg(&col[e]);
    int r = __ldg(&row[e]);
    float4 v = __ldg(&src[c * 16 + j]);
    float* p = dst + (long long)r * CC + j * 4;
    asm volatile("red.global.add.v4.f32 [%0], {%1, %2, %3, %4};"
                 :: "l"(p), "f"(v.x * wv), "f"(v.y * wv), "f"(v.z * wv), "f"(v.w * wv)
                 : "memory");
}

__global__ void prop1_kernel(const int* __restrict__ row, const int* __restrict__ col,
                             const float4* __restrict__ x) {
    long long idx = (long long)blockIdx.x * blockDim.x + threadIdx.x;
    if (idx < (long long)NE * 16) prop_body(idx, row, col, x, (float*)g_T1);
}

__global__ void prop2_kernel(const int* __restrict__ row, const int* __restrict__ col) {
    long long idx = (long long)blockIdx.x * blockDim.x + threadIdx.x;
    if (idx < (long long)NE * 16) prop_body(idx, row, col, g_T1, (float*)g_P2);
}

// ---------------------------------------------------------------------------
// Epilogue: out = relu( x@(W0-W2) + T1@W1 + P2@(2*W2) + b )
// Fused GEMM [Nx192] @ [192x64]; W tiles staged in shared (48 KB).
// Block: 64 nodes x 64 outputs, 256 threads; thread = 1 node x 16 outputs.
// ---------------------------------------------------------------------------
__global__ void __launch_bounds__(256) epi_kernel(const float* __restrict__ x,
                                                  const float* __restrict__ W,
                                                  const float* __restrict__ b,
                                                  float* __restrict__ out) {
    __shared__ float ws[192 * 64];  // [W0-W2 ; W1 ; 2*W2], each [64][64]

    int tid = threadIdx.x;
    for (int i = tid; i < 4096; i += 256) {
        float w0 = W[i];
        float w1 = W[4096 + i];
        float w2 = W[8192 + i];
        ws[i]        = w0 - w2;
        ws[4096 + i] = w1;
        ws[8192 + i] = 2.0f * w2;
    }
    __syncthreads();

    int node_local = tid >> 2;   // 0..63
    int og = tid & 3;            // output group: 16 outputs each
    int n = blockIdx.x * 64 + node_local;
    if (n >= NN) return;

    float acc[16];
#pragma unroll
    for (int o = 0; o < 16; o++) acc[o] = 0.0f;

    const float4* a0 = (const float4*)(x + (long long)n * CC);
    const float4* a1 = g_T1 + n * 16;
    const float4* a2 = g_P2 + n * 16;

#pragma unroll
    for (int part = 0; part < 3; part++) {
        const float4* a4 = (part == 0) ? a0 : (part == 1) ? a1 : a2;
        const float* wsp = ws + part * 4096;
#pragma unroll 2
        for (int c4 = 0; c4 < 16; c4++) {
            float4 a = __ldg(&a4[c4]);
            float av[4] = {a.x, a.y, a.z, a.w};
#pragma unroll
            for (int t = 0; t < 4; t++) {
                const float4* wr = (const float4*)(wsp + (c4 * 4 + t) * 64 + og * 16);
#pragma unroll
                for (int q = 0; q < 4; q++) {
                    float4 wv = wr[q];
                    acc[q * 4 + 0] = fmaf(av[t], wv.x, acc[q * 4 + 0]);
                    acc[q * 4 + 1] = fmaf(av[t], wv.y, acc[q * 4 + 1]);
                    acc[q * 4 + 2] = fmaf(av[t], wv.z, acc[q * 4 + 2]);
                    acc[q * 4 + 3] = fmaf(av[t], wv.w, acc[q * 4 + 3]);
                }
            }
        }
    }

    int jbase = og * 16;
    float4* outp = (float4*)(out + (long long)n * CC + jbase);
#pragma unroll
    for (int q = 0; q < 4; q++) {
        float4 r;
        r.x = fmaxf(acc[q * 4 + 0] + __ldg(&b[jbase + q * 4 + 0]), 0.0f);
        r.y = fmaxf(acc[q * 4 + 1] + __ldg(&b[jbase + q * 4 + 1]), 0.0f);
        r.z = fmaxf(acc[q * 4 + 2] + __ldg(&b[jbase + q * 4 + 2]), 0.0f);
        r.w = fmaxf(acc[q * 4 + 3] + __ldg(&b[jbase + q * 4 + 3]), 0.0f);
        outp[q] = r;
    }
}

// ---------------------------------------------------------------------------
// Launch
// ---------------------------------------------------------------------------
extern "C" void kernel_launch(void* const* d_in, const int* in_sizes, int n_in,
                              void* d_out, int out_size) {
    const float* x  = (const float*)d_in[0];   // [N, 64]
    const int*   ei = (const int*)d_in[1];     // [2, E]
    const float* ew = (const float*)d_in[2];   // [E]
    const float* W  = (const float*)d_in[3];   // [3, 64, 64]
    const float* b  = (const float*)d_in[4];   // [64]
    float* out = (float*)d_out;                // [N, 64]

    const int E = in_sizes[2];                 // 800000
    const int* row = ei;
    const int* col = ei + E;

    zero_kernel<<<1024, 256>>>();
    deg_kernel<<<(NE + 255) / 256, 256>>>(row, ew);
    weight_kernel<<<(NE + 255) / 256, 256>>>(row, col, ew);

    const long long work = (long long)NE * 16;
    const int pgrid = (int)((work + 255) / 256);
    prop1_kernel<<<pgrid, 256>>>(row, col, (const float4*)x);
    prop2_kernel<<<pgrid, 256>>>(row, col);

    epi_kernel<<<(NN + 63) / 64, 256>>>(x, W, b, out);
}

// round 7
// speedup vs baseline: 1.6710x; 1.6710x over previous
#include <cuda_runtime.h>

#define NN 50000
#define NE 800000
#define CC 64
#define NBLK ((NN + 255) / 256)   // 196

// ---------------- device scratch (no allocations allowed) ----------------
__device__ float  g_deg[NN];
__device__ int    g_cnt[NN];
__device__ int    g_bsum[NBLK];
__device__ int    g_boff[NBLK];
__device__ int    g_rowstart[NN + 1];
__device__ int    g_pos[NN];
__device__ float2 g_ecsr[NE];            // {col (bit-cast int), w} sorted by row
__device__ float4 g_T1[NN * (CC / 4)];   // T1 = L_hat @ x
__device__ float4 g_P2[NN * (CC / 4)];   // P2 = L_hat @ T1

// ---------------------------------------------------------------------------
// Zero deg + cnt
// ---------------------------------------------------------------------------
__global__ void zero_kernel() {
    int i = blockIdx.x * blockDim.x + threadIdx.x;
    int stride = gridDim.x * blockDim.x;
    for (int j = i; j < NN; j += stride) {
        g_deg[j] = 0.0f;
        g_cnt[j] = 0;
    }
}

// ---------------------------------------------------------------------------
// deg[r] += ew ; cnt[r] += 1
// ---------------------------------------------------------------------------
__global__ void deg_kernel(const int* __restrict__ row, const float* __restrict__ ew) {
    int e = blockIdx.x * blockDim.x + threadIdx.x;
    if (e < NE) {
        int r = row[e];
        atomicAdd(&g_deg[r], ew[e]);
        atomicAdd(&g_cnt[r], 1);
    }
}

// ---------------------------------------------------------------------------
// Scan step 1: per-block sums of cnt
// ---------------------------------------------------------------------------
__global__ void scan1_kernel() {
    __shared__ int s[256];
    int t = threadIdx.x;
    int idx = blockIdx.x * 256 + t;
    s[t] = (idx < NN) ? g_cnt[idx] : 0;
    __syncthreads();
    for (int off = 128; off > 0; off >>= 1) {
        if (t < off) s[t] += s[t + off];
        __syncthreads();
    }
    if (t == 0) g_bsum[blockIdx.x] = s[0];
}

// ---------------------------------------------------------------------------
// Scan step 2: spine (exclusive scan over NBLK block sums), 1 block
// ---------------------------------------------------------------------------
__global__ void scan2_kernel() {
    __shared__ int s[256];
    int t = threadIdx.x;
    int v = (t < NBLK) ? g_bsum[t] : 0;
    s[t] = v;
    __syncthreads();
    for (int off = 1; off < 256; off <<= 1) {
        int add = (t >= off) ? s[t - off] : 0;
        __syncthreads();
        s[t] += add;
        __syncthreads();
    }
    if (t < NBLK) g_boff[t] = s[t] - v;
    if (t == 0) g_rowstart[NN] = NE;
}

// ---------------------------------------------------------------------------
// Scan step 3: intra-block exclusive scan + spine offset -> rowstart, pos
// ---------------------------------------------------------------------------
__global__ void scan3_kernel() {
    __shared__ int s[256];
    int t = threadIdx.x;
    int idx = blockIdx.x * 256 + t;
    int v = (idx < NN) ? g_cnt[idx] : 0;
    s[t] = v;
    __syncthreads();
    for (int off = 1; off < 256; off <<= 1) {
        int add = (t >= off) ? s[t - off] : 0;
        __syncthreads();
        s[t] += add;
        __syncthreads();
    }
    if (idx < NN) {
        int excl = s[t] - v + g_boff[blockIdx.x];
        g_rowstart[idx] = excl;
        g_pos[idx] = excl;
    }
}

// ---------------------------------------------------------------------------
// Scatter edges into CSR, folding in the normalized Laplacian weight:
//   w = -rsqrt(deg[row]) * ew * rsqrt(deg[col])
// ---------------------------------------------------------------------------
__global__ void scatter_kernel(const int* __restrict__ row, const int* __restrict__ col,
                               const float* __restrict__ ew) {
    int e = blockIdx.x * blockDim.x + threadIdx.x;
    if (e < NE) {
        int r = row[e];
        int c = col[e];
        float dr = __ldg(&g_deg[r]);
        float dc = __ldg(&g_deg[c]);
        float ir = (dr > 0.0f) ? rsqrtf(dr) : 0.0f;
        float ic = (dc > 0.0f) ? rsqrtf(dc) : 0.0f;
        float w = -ir * ew[e] * ic;
        int slot = atomicAdd(&g_pos[r], 1);
        g_ecsr[slot] = make_float2(__int_as_float(c), w);
    }
}

// ---------------------------------------------------------------------------
// Row-centric propagation: 16-thread group per node, float4 per thread.
// No atomics: each group owns its output row. 4-edge unroll for MLP.
// NOTE: dst/src globals are bound INSIDE device code (never passed from host:
// a __device__ symbol used as a host-side kernel arg is the host shadow
// address, which GB300's ATS silently accepts -> wrong memory, no fault).
// ---------------------------------------------------------------------------
__device__ __forceinline__ void prop_impl(const float4* __restrict__ src,
                                          float4* __restrict__ dst,
                                          int gid) {
    int n = gid >> 4;
    int j = gid & 15;
    if (n >= NN) return;

    int s = __ldg(&g_rowstart[n]);
    int e = __ldg(&g_rowstart[n + 1]);

    float4 acc = make_float4(0.f, 0.f, 0.f, 0.f);
    int i = s;
    for (; i + 3 < e; i += 4) {
        float2 p0 = __ldg(&g_ecsr[i + 0]);
        float2 p1 = __ldg(&g_ecsr[i + 1]);
        float2 p2 = __ldg(&g_ecsr[i + 2]);
        float2 p3 = __ldg(&g_ecsr[i + 3]);
        float4 v0 = __ldg(&src[__float_as_int(p0.x) * 16 + j]);
        float4 v1 = __ldg(&src[__float_as_int(p1.x) * 16 + j]);
        float4 v2 = __ldg(&src[__float_as_int(p2.x) * 16 + j]);
        float4 v3 = __ldg(&src[__float_as_int(p3.x) * 16 + j]);
        acc.x = fmaf(p0.y, v0.x, acc.x); acc.y = fmaf(p0.y, v0.y, acc.y);
        acc.z = fmaf(p0.y, v0.z, acc.z); acc.w = fmaf(p0.y, v0.w, acc.w);
        acc.x = fmaf(p1.y, v1.x, acc.x); acc.y = fmaf(p1.y, v1.y, acc.y);
        acc.z = fmaf(p1.y, v1.z, acc.z); acc.w = fmaf(p1.y, v1.w, acc.w);
        acc.x = fmaf(p2.y, v2.x, acc.x); acc.y = fmaf(p2.y, v2.y, acc.y);
        acc.z = fmaf(p2.y, v2.z, acc.z); acc.w = fmaf(p2.y, v2.w, acc.w);
        acc.x = fmaf(p3.y, v3.x, acc.x); acc.y = fmaf(p3.y, v3.y, acc.y);
        acc.z = fmaf(p3.y, v3.z, acc.z); acc.w = fmaf(p3.y, v3.w, acc.w);
    }
    for (; i < e; i++) {
        float2 p = __ldg(&g_ecsr[i]);
        float4 v = __ldg(&src[__float_as_int(p.x) * 16 + j]);
        acc.x = fmaf(p.y, v.x, acc.x); acc.y = fmaf(p.y, v.y, acc.y);
        acc.z = fmaf(p.y, v.z, acc.z); acc.w = fmaf(p.y, v.w, acc.w);
    }
    dst[n * 16 + j] = acc;
}

__global__ void __launch_bounds__(256) prop1_kernel(const float4* __restrict__ x) {
    int gid = blockIdx.x * blockDim.x + threadIdx.x;
    prop_impl(x, g_T1, gid);   // g_T1 bound in device code: correct address
}

__global__ void __launch_bounds__(256) prop2_kernel() {
    int gid = blockIdx.x * blockDim.x + threadIdx.x;
    prop_impl(g_T1, g_P2, gid);
}

// ---------------------------------------------------------------------------
// Epilogue: out = relu( x@(W0-W2) + T1@W1 + P2@(2*W2) + b )
// Block: 128 nodes x 64 outputs, 256 threads; thread = 2 nodes x 16 outputs.
// ---------------------------------------------------------------------------
__global__ void __launch_bounds__(256) epi_kernel(const float* __restrict__ x,
                                                  const float* __restrict__ W,
                                                  const float* __restrict__ b,
                                                  float* __restrict__ out) {
    __shared__ float ws[192 * 64];  // [W0-W2 ; W1 ; 2*W2], each [64][64]

    int tid = threadIdx.x;
    for (int i = tid; i < 4096; i += 256) {
        float w0 = W[i];
        float w1 = W[4096 + i];
        float w2 = W[8192 + i];
        ws[i]        = w0 - w2;
        ws[4096 + i] = w1;
        ws[8192 + i] = 2.0f * w2;
    }
    __syncthreads();

    int np = tid >> 2;           // 0..63 -> pair of nodes
    int og = tid & 3;            // output group: 16 outputs each
    int n0 = blockIdx.x * 128 + np * 2;
    int n1 = n0 + 1;
    if (n0 >= NN) return;
    bool has1 = (n1 < NN);

    float acc0[16], acc1[16];
#pragma unroll
    for (int o = 0; o < 16; o++) { acc0[o] = 0.0f; acc1[o] = 0.0f; }

    const float4* a0x = (const float4*)(x + (long long)n0 * CC);
    const float4* a1x = (const float4*)(x + (long long)n1 * CC);

#pragma unroll
    for (int part = 0; part < 3; part++) {
        const float4* s0 = (part == 0) ? a0x : (part == 1) ? (g_T1 + n0 * 16) : (g_P2 + n0 * 16);
        const float4* s1 = (part == 0) ? a1x : (part == 1) ? (g_T1 + n1 * 16) : (g_P2 + n1 * 16);
        const float* wsp = ws + part * 4096;
        for (int c4 = 0; c4 < 16; c4++) {
            float4 a0 = __ldg(&s0[c4]);
            float4 a1 = has1 ? __ldg(&s1[c4]) : make_float4(0.f, 0.f, 0.f, 0.f);
            float av0[4] = {a0.x, a0.y, a0.z, a0.w};
            float av1[4] = {a1.x, a1.y, a1.z, a1.w};
#pragma unroll
            for (int t = 0; t < 4; t++) {
                const float4* wr = (const float4*)(wsp + (c4 * 4 + t) * 64 + og * 16);
#pragma unroll
                for (int q = 0; q < 4; q++) {
                    float4 wv = wr[q];
                    acc0[q * 4 + 0] = fmaf(av0[t], wv.x, acc0[q * 4 + 0]);
                    acc0[q * 4 + 1] = fmaf(av0[t], wv.y, acc0[q * 4 + 1]);
                    acc0[q * 4 + 2] = fmaf(av0[t], wv.z, acc0[q * 4 + 2]);
                    acc0[q * 4 + 3] = fmaf(av0[t], wv.w, acc0[q * 4 + 3]);
                    acc1[q * 4 + 0] = fmaf(av1[t], wv.x, acc1[q * 4 + 0]);
                    acc1[q * 4 + 1] = fmaf(av1[t], wv.y, acc1[q * 4 + 1]);
                    acc1[q * 4 + 2] = fmaf(av1[t], wv.z, acc1[q * 4 + 2]);
                    acc1[q * 4 + 3] = fmaf(av1[t], wv.w, acc1[q * 4 + 3]);
                }
            }
        }
    }

    int jbase = og * 16;
    float4* outp0 = (float4*)(out + (long long)n0 * CC + jbase);
#pragma unroll
    for (int q = 0; q < 4; q++) {
        float4 r;
        r.x = fmaxf(acc0[q * 4 + 0] + __ldg(&b[jbase + q * 4 + 0]), 0.0f);
        r.y = fmaxf(acc0[q * 4 + 1] + __ldg(&b[jbase + q * 4 + 1]), 0.0f);
        r.z = fmaxf(acc0[q * 4 + 2] + __ldg(&b[jbase + q * 4 + 2]), 0.0f);
        r.w = fmaxf(acc0[q * 4 + 3] + __ldg(&b[jbase + q * 4 + 3]), 0.0f);
        outp0[q] = r;
    }
    if (has1) {
        float4* outp1 = (float4*)(out + (long long)n1 * CC + jbase);
#pragma unroll
        for (int q = 0; q < 4; q++) {
            float4 r;
            r.x = fmaxf(acc1[q * 4 + 0] + __ldg(&b[jbase + q * 4 + 0]), 0.0f);
            r.y = fmaxf(acc1[q * 4 + 1] + __ldg(&b[jbase + q * 4 + 1]), 0.0f);
            r.z = fmaxf(acc1[q * 4 + 2] + __ldg(&b[jbase + q * 4 + 2]), 0.0f);
            r.w = fmaxf(acc1[q * 4 + 3] + __ldg(&b[jbase + q * 4 + 3]), 0.0f);
            outp1[q] = r;
        }
    }
}

// ---------------------------------------------------------------------------
// Launch
// ---------------------------------------------------------------------------
extern "C" void kernel_launch(void* const* d_in, const int* in_sizes, int n_in,
                              void* d_out, int out_size) {
    const float* x  = (const float*)d_in[0];   // [N, 64]
    const int*   ei = (const int*)d_in[1];     // [2, E]
    const float* ew = (const float*)d_in[2];   // [E]
    const float* W  = (const float*)d_in[3];   // [3, 64, 64]
    const float* b  = (const float*)d_in[4];   // [64]
    float* out = (float*)d_out;                // [N, 64]

    const int E = in_sizes[2];                 // 800000
    const int* row = ei;
    const int* col = ei + E;

    const int egrid = (NE + 255) / 256;

    zero_kernel<<<256, 256>>>();
    deg_kernel<<<egrid, 256>>>(row, ew);
    scan1_kernel<<<NBLK, 256>>>();
    scan2_kernel<<<1, 256>>>();
    scan3_kernel<<<NBLK, 256>>>();
    scatter_kernel<<<egrid, 256>>>(row, col, ew);

    const int pgrid = (NN * 16 + 255) / 256;
    prop1_kernel<<<pgrid, 256>>>((const float4*)x);
    prop2_kernel<<<pgrid, 256>>>();

    epi_kernel<<<(NN + 127) / 128, 256>>>(x, W, b, out);
    (void)E; (void)n_in; (void)out_size;
}

// round 8
// speedup vs baseline: 1.6876x; 1.0100x over previous
#include <cuda_runtime.h>

#define NN 50000
#define NE 800000
#define CC 64
#define NBLK ((NN + 255) / 256)   // 196

// ---------------- device scratch (no allocations allowed) ----------------
__device__ float  g_deg[NN];
__device__ int    g_cnt[NN];
__device__ int    g_bsum[NBLK];
__device__ int    g_rowstart[NN + 1];
__device__ int    g_pos[NN];
__device__ float2 g_ecsr[NE];            // {col (bit-cast int), w} sorted by row
__device__ float4 g_T1[NN * (CC / 4)];   // T1 = L_hat @ x
__device__ float4 g_P2[NN * (CC / 4)];   // P2 = L_hat @ T1

// Packed fp32x2 FMA (sm_103a FFMA2 — only reachable via PTX)
#define FMA2(d, a, b) \
    asm("fma.rn.f32x2 %0, %1, %2, %0;" : "+l"(d) : "l"(a), "l"(b))
#define PACK2(d, lo, hi) \
    asm("mov.b64 %0, {%1, %2};" : "=l"(d) : "f"(lo), "f"(hi))
#define UNPACK2(lo, hi, s) \
    asm("mov.b64 {%0, %1}, %2;" : "=f"(lo), "=f"(hi) : "l"(s))

// ---------------------------------------------------------------------------
// Zero deg + cnt (+ rowstart sentinel)
// ---------------------------------------------------------------------------
__global__ void zero_kernel() {
    int i = blockIdx.x * blockDim.x + threadIdx.x;
    int stride = gridDim.x * blockDim.x;
    for (int j = i; j < NN; j += stride) {
        g_deg[j] = 0.0f;
        g_cnt[j] = 0;
    }
    if (i == 0) g_rowstart[NN] = NE;
}

// ---------------------------------------------------------------------------
// deg[r] += ew ; cnt[r] += 1
// ---------------------------------------------------------------------------
__global__ void deg_kernel(const int* __restrict__ row, const float* __restrict__ ew) {
    int e = blockIdx.x * blockDim.x + threadIdx.x;
    if (e < NE) {
        int r = row[e];
        atomicAdd(&g_deg[r], ew[e]);
        atomicAdd(&g_cnt[r], 1);
    }
}

// ---------------------------------------------------------------------------
// Scan step 1: per-block sums of cnt
// ---------------------------------------------------------------------------
__global__ void scan1_kernel() {
    __shared__ int s[256];
    int t = threadIdx.x;
    int idx = blockIdx.x * 256 + t;
    s[t] = (idx < NN) ? g_cnt[idx] : 0;
    __syncthreads();
    for (int off = 128; off > 0; off >>= 1) {
        if (t < off) s[t] += s[t + off];
        __syncthreads();
    }
    if (t == 0) g_bsum[blockIdx.x] = s[0];
}

// ---------------------------------------------------------------------------
// Scan step 2 (fused spine + local): each block sums the preceding block
// sums itself (<=196 ints), then does its local exclusive scan.
// ---------------------------------------------------------------------------
__global__ void scan2_kernel() {
    __shared__ int s[256];
    __shared__ int base_sh;
    int t = threadIdx.x;
    int idx = blockIdx.x * 256 + t;

    // spine: sum of g_bsum[0 .. blockIdx.x)
    int part = 0;
    for (int j = t; j < blockIdx.x; j += 256) part += g_bsum[j];
    s[t] = part;
    __syncthreads();
    for (int off = 128; off > 0; off >>= 1) {
        if (t < off) s[t] += s[t + off];
        __syncthreads();
    }
    if (t == 0) base_sh = s[0];
    __syncthreads();
    int base = base_sh;
    __syncthreads();

    // local inclusive scan (Hillis-Steele)
    int v = (idx < NN) ? g_cnt[idx] : 0;
    s[t] = v;
    __syncthreads();
    for (int off = 1; off < 256; off <<= 1) {
        int add = (t >= off) ? s[t - off] : 0;
        __syncthreads();
        s[t] += add;
        __syncthreads();
    }
    if (idx < NN) {
        int excl = s[t] - v + base;
        g_rowstart[idx] = excl;
        g_pos[idx] = excl;
    }
}

// ---------------------------------------------------------------------------
// Scatter edges into CSR, folding in the normalized Laplacian weight:
//   w = -rsqrt(deg[row]) * ew * rsqrt(deg[col])
// ---------------------------------------------------------------------------
__global__ void scatter_kernel(const int* __restrict__ row, const int* __restrict__ col,
                               const float* __restrict__ ew) {
    int e = blockIdx.x * blockDim.x + threadIdx.x;
    if (e < NE) {
        int r = row[e];
        int c = col[e];
        float dr = __ldg(&g_deg[r]);
        float dc = __ldg(&g_deg[c]);
        float ir = (dr > 0.0f) ? rsqrtf(dr) : 0.0f;
        float ic = (dc > 0.0f) ? rsqrtf(dc) : 0.0f;
        float w = -ir * ew[e] * ic;
        int slot = atomicAdd(&g_pos[r], 1);
        g_ecsr[slot] = make_float2(__int_as_float(c), w);
    }
}

// ---------------------------------------------------------------------------
// Row-centric propagation: 16-thread group per node, float4 per thread.
// No atomics. 8-edge unroll for MLP (L2 gather latency ~240cyc to hide).
// dst/src device globals bound ONLY inside device code (host shadow trap).
// ---------------------------------------------------------------------------
__device__ __forceinline__ void prop_impl(const float4* __restrict__ src,
                                          float4* __restrict__ dst,
                                          int gid) {
    int n = gid >> 4;
    int j = gid & 15;
    if (n >= NN) return;

    int s = __ldg(&g_rowstart[n]);
    int e = __ldg(&g_rowstart[n + 1]);

    float4 acc = make_float4(0.f, 0.f, 0.f, 0.f);
    int i = s;
    for (; i + 7 < e; i += 8) {
        float2 p[8];
        float4 v[8];
#pragma unroll
        for (int u = 0; u < 8; u++) p[u] = __ldg(&g_ecsr[i + u]);
#pragma unroll
        for (int u = 0; u < 8; u++) v[u] = __ldg(&src[__float_as_int(p[u].x) * 16 + j]);
#pragma unroll
        for (int u = 0; u < 8; u++) {
            acc.x = fmaf(p[u].y, v[u].x, acc.x);
            acc.y = fmaf(p[u].y, v[u].y, acc.y);
            acc.z = fmaf(p[u].y, v[u].z, acc.z);
            acc.w = fmaf(p[u].y, v[u].w, acc.w);
        }
    }
    for (; i + 3 < e; i += 4) {
        float2 p[4];
        float4 v[4];
#pragma unroll
        for (int u = 0; u < 4; u++) p[u] = __ldg(&g_ecsr[i + u]);
#pragma unroll
        for (int u = 0; u < 4; u++) v[u] = __ldg(&src[__float_as_int(p[u].x) * 16 + j]);
#pragma unroll
        for (int u = 0; u < 4; u++) {
            acc.x = fmaf(p[u].y, v[u].x, acc.x);
            acc.y = fmaf(p[u].y, v[u].y, acc.y);
            acc.z = fmaf(p[u].y, v[u].z, acc.z);
            acc.w = fmaf(p[u].y, v[u].w, acc.w);
        }
    }
    for (; i < e; i++) {
        float2 p = __ldg(&g_ecsr[i]);
        float4 v = __ldg(&src[__float_as_int(p.x) * 16 + j]);
        acc.x = fmaf(p.y, v.x, acc.x);
        acc.y = fmaf(p.y, v.y, acc.y);
        acc.z = fmaf(p.y, v.z, acc.z);
        acc.w = fmaf(p.y, v.w, acc.w);
    }
    dst[n * 16 + j] = acc;
}

__global__ void __launch_bounds__(256) prop1_kernel(const float4* __restrict__ x) {
    int gid = blockIdx.x * blockDim.x + threadIdx.x;
    prop_impl(x, g_T1, gid);
}

__global__ void __launch_bounds__(256) prop2_kernel() {
    int gid = blockIdx.x * blockDim.x + threadIdx.x;
    prop_impl(g_T1, g_P2, gid);
}

// ---------------------------------------------------------------------------
// Epilogue: out = relu( x@(W0-W2) + T1@W1 + P2@(2*W2) + b )
// Packed f32x2 FMA (FFMA2): 2 nodes x 16 outputs per thread, accumulators
// held as 8 packed f32x2 per node. W rows read from shared as 128-bit.
// ---------------------------------------------------------------------------
__global__ void __launch_bounds__(256) epi_kernel(const float* __restrict__ x,
                                                  const float* __restrict__ W,
                                                  const float* __restrict__ b,
                                                  float* __restrict__ out) {
    __shared__ float ws[192 * 64];  // [W0-W2 ; W1 ; 2*W2], each [64][64]

    int tid = threadIdx.x;
    for (int i = tid; i < 4096; i += 256) {
        float w0 = W[i];
        float w1 = W[4096 + i];
        float w2 = W[8192 + i];
        ws[i]        = w0 - w2;
        ws[4096 + i] = w1;
        ws[8192 + i] = 2.0f * w2;
    }
    __syncthreads();

    int np = tid >> 2;           // 0..63 -> node pair
    int og = tid & 3;            // output group: 16 outputs
    int n0 = blockIdx.x * 128 + np * 2;
    int n1 = n0 + 1;
    if (n0 >= NN) return;
    bool has1 = (n1 < NN);

    unsigned long long acc0[8], acc1[8];   // 16 outputs as 8 f32x2 each
#pragma unroll
    for (int o = 0; o < 8; o++) { acc0[o] = 0ULL; acc1[o] = 0ULL; }

    const float4* a0x = (const float4*)(x + (long long)n0 * CC);
    const float4* a1x = (const float4*)(x + (long long)n1 * CC);

#pragma unroll
    for (int part = 0; part < 3; part++) {
        const float4* s0 = (part == 0) ? a0x : (part == 1) ? (g_T1 + n0 * 16) : (g_P2 + n0 * 16);
        const float4* s1 = (part == 0) ? a1x : (part == 1) ? (g_T1 + n1 * 16) : (g_P2 + n1 * 16);
        const float* wsp = ws + part * 4096;
        for (int c4 = 0; c4 < 16; c4++) {
            float4 a0 = __ldg(&s0[c4]);
            float4 a1 = has1 ? __ldg(&s1[c4]) : make_float4(0.f, 0.f, 0.f, 0.f);
            float av0[4] = {a0.x, a0.y, a0.z, a0.w};
            float av1[4] = {a1.x, a1.y, a1.z, a1.w};
#pragma unroll
            for (int t = 0; t < 4; t++) {
                unsigned long long pa0, pa1;
                PACK2(pa0, av0[t], av0[t]);
                PACK2(pa1, av1[t], av1[t]);
                // 16 W floats for this k-row = 4 x 128-bit shared loads
                const ulonglong2* wp =
                    (const ulonglong2*)(wsp + (c4 * 4 + t) * 64 + og * 16);
#pragma unroll
                for (int q = 0; q < 4; q++) {
                    ulonglong2 wv = wp[q];
                    FMA2(acc0[q * 2 + 0], pa0, wv.x);
                    FMA2(acc0[q * 2 + 1], pa0, wv.y);
                    FMA2(acc1[q * 2 + 0], pa1, wv.x);
                    FMA2(acc1[q * 2 + 1], pa1, wv.y);
                }
            }
        }
    }

    int jbase = og * 16;
    float4* outp0 = (float4*)(out + (long long)n0 * CC + jbase);
#pragma unroll
    for (int q = 0; q < 4; q++) {
        float lo0, hi0, lo1, hi1;
        UNPACK2(lo0, hi0, acc0[q * 2 + 0]);
        UNPACK2(lo1, hi1, acc0[q * 2 + 1]);
        float4 r;
        r.x = fmaxf(lo0 + __ldg(&b[jbase + q * 4 + 0]), 0.0f);
        r.y = fmaxf(hi0 + __ldg(&b[jbase + q * 4 + 1]), 0.0f);
        r.z = fmaxf(lo1 + __ldg(&b[jbase + q * 4 + 2]), 0.0f);
        r.w = fmaxf(hi1 + __ldg(&b[jbase + q * 4 + 3]), 0.0f);
        outp0[q] = r;
    }
    if (has1) {
        float4* outp1 = (float4*)(out + (long long)n1 * CC + jbase);
#pragma unroll
        for (int q = 0; q < 4; q++) {
            float lo0, hi0, lo1, hi1;
            UNPACK2(lo0, hi0, acc1[q * 2 + 0]);
            UNPACK2(lo1, hi1, acc1[q * 2 + 1]);
            float4 r;
            r.x = fmaxf(lo0 + __ldg(&b[jbase + q * 4 + 0]), 0.0f);
            r.y = fmaxf(hi0 + __ldg(&b[jbase + q * 4 + 1]), 0.0f);
            r.z = fmaxf(lo1 + __ldg(&b[jbase + q * 4 + 2]), 0.0f);
            r.w = fmaxf(hi1 + __ldg(&b[jbase + q * 4 + 3]), 0.0f);
            outp1[q] = r;
        }
    }
}

// ---------------------------------------------------------------------------
// Launch
// ---------------------------------------------------------------------------
extern "C" void kernel_launch(void* const* d_in, const int* in_sizes, int n_in,
                              void* d_out, int out_size) {
    const float* x  = (const float*)d_in[0];   // [N, 64]
    const int*   ei = (const int*)d_in[1];     // [2, E]
    const float* ew = (const float*)d_in[2];   // [E]
    const float* W  = (const float*)d_in[3];   // [3, 64, 64]
    const float* b  = (const float*)d_in[4];   // [64]
    float* out = (float*)d_out;                // [N, 64]

    const int E = in_sizes[2];                 // 800000
    const int* row = ei;
    const int* col = ei + E;

    const int egrid = (NE + 255) / 256;

    zero_kernel<<<256, 256>>>();
    deg_kernel<<<egrid, 256>>>(row, ew);
    scan1_kernel<<<NBLK, 256>>>();
    scan2_kernel<<<NBLK, 256>>>();
    scatter_kernel<<<egrid, 256>>>(row, col, ew);

    const int pgrid = (NN * 16 + 255) / 256;
    prop1_kernel<<<pgrid, 256>>>((const float4*)x);
    prop2_kernel<<<pgrid, 256>>>();

    epi_kernel<<<(NN + 127) / 128, 256>>>(x, W, b, out);
    (void)E; (void)n_in; (void)out_size;
}

// round 12
// speedup vs baseline: 1.7549x; 1.0399x over previous
#include <cuda_runtime.h>
#include <cuda_fp16.h>

#define NN 50000
#define NE 800000
#define CC 64
#define NBLK ((NN + 255) / 256)   // 196

// ---------------- device scratch (no allocations allowed) ----------------
__device__ float  g_deg[NN];
__device__ int    g_cnt[NN];
__device__ int    g_bsum[NBLK];
__device__ int    g_rowstart[NN + 1];
__device__ int    g_pos[NN];
__device__ float2 g_ecsr[NE];          // {col (bit-cast int), w} sorted by row
__device__ __half g_xh[NN * CC];       // fp16 copy of x (gather source)
__device__ __half g_T1h[NN * CC];      // T1 = L_hat @ x      (fp16)
__device__ __half g_P2h[NN * CC];      // P2 = L_hat @ T1     (fp16)

// Packed fp32x2 FMA (sm_103a FFMA2 — only reachable via PTX)
#define FMA2(d, a, b) \
    asm("fma.rn.f32x2 %0, %1, %2, %0;" : "+l"(d) : "l"(a), "l"(b))
#define PACK2(d, lo, hi) \
    asm("mov.b64 %0, {%1, %2};" : "=l"(d) : "f"(lo), "f"(hi))
#define UNPACK2(lo, hi, s) \
    asm("mov.b64 {%0, %1}, %2;" : "=f"(lo), "=f"(hi) : "l"(s))

// ---------------------------------------------------------------------------
// Zero deg/cnt, set sentinel, and convert x -> fp16 (fused; independent work)
// ---------------------------------------------------------------------------
__global__ void zero_convert_kernel(const float4* __restrict__ x) {
    int i = blockIdx.x * blockDim.x + threadIdx.x;
    int stride = gridDim.x * blockDim.x;
    for (int j = i; j < NN; j += stride) {
        g_deg[j] = 0.0f;
        g_cnt[j] = 0;
    }
    // convert in chunks of 8 floats -> 8 halfs (uint4 store)
    const int chunks = NN * CC / 8;   // 400000
    uint4* dst = (uint4*)g_xh;
    for (int c = i; c < chunks; c += stride) {
        float4 a = __ldg(&x[c * 2 + 0]);
        float4 b = __ldg(&x[c * 2 + 1]);
        half2 h0 = __floats2half2_rn(a.x, a.y);
        half2 h1 = __floats2half2_rn(a.z, a.w);
        half2 h2 = __floats2half2_rn(b.x, b.y);
        half2 h3 = __floats2half2_rn(b.z, b.w);
        uint4 o;
        o.x = *(unsigned*)&h0; o.y = *(unsigned*)&h1;
        o.z = *(unsigned*)&h2; o.w = *(unsigned*)&h3;
        dst[c] = o;
    }
    if (i == 0) g_rowstart[NN] = NE;
}

// ---------------------------------------------------------------------------
// deg[r] += ew ; cnt[r] += 1
// ---------------------------------------------------------------------------
__global__ void deg_kernel(const int* __restrict__ row, const float* __restrict__ ew) {
    int e = blockIdx.x * blockDim.x + threadIdx.x;
    if (e < NE) {
        int r = row[e];
        atomicAdd(&g_deg[r], ew[e]);
        atomicAdd(&g_cnt[r], 1);
    }
}

// ---------------------------------------------------------------------------
// Scan step 1: per-block sums of cnt
// ---------------------------------------------------------------------------
__global__ void scan1_kernel() {
    __shared__ int s[256];
    int t = threadIdx.x;
    int idx = blockIdx.x * 256 + t;
    s[t] = (idx < NN) ? g_cnt[idx] : 0;
    __syncthreads();
    for (int off = 128; off > 0; off >>= 1) {
        if (t < off) s[t] += s[t + off];
        __syncthreads();
    }
    if (t == 0) g_bsum[blockIdx.x] = s[0];
}

// ---------------------------------------------------------------------------
// Scan step 2 (fused spine + local exclusive scan)
// ---------------------------------------------------------------------------
__global__ void scan2_kernel() {
    __shared__ int s[256];
    __shared__ int base_sh;
    int t = threadIdx.x;
    int idx = blockIdx.x * 256 + t;

    int part = 0;
    for (int j = t; j < blockIdx.x; j += 256) part += g_bsum[j];
    s[t] = part;
    __syncthreads();
    for (int off = 128; off > 0; off >>= 1) {
        if (t < off) s[t] += s[t + off];
        __syncthreads();
    }
    if (t == 0) base_sh = s[0];
    __syncthreads();
    int base = base_sh;
    __syncthreads();

    int v = (idx < NN) ? g_cnt[idx] : 0;
    s[t] = v;
    __syncthreads();
    for (int off = 1; off < 256; off <<= 1) {
        int add = (t >= off) ? s[t - off] : 0;
        __syncthreads();
        s[t] += add;
        __syncthreads();
    }
    if (idx < NN) {
        int excl = s[t] - v + base;
        g_rowstart[idx] = excl;
        g_pos[idx] = excl;
    }
}

// ---------------------------------------------------------------------------
// Scatter edges into CSR with normalized Laplacian weight folded in
// ---------------------------------------------------------------------------
__global__ void scatter_kernel(const int* __restrict__ row, const int* __restrict__ col,
                               const float* __restrict__ ew) {
    int e = blockIdx.x * blockDim.x + threadIdx.x;
    if (e < NE) {
        int r = row[e];
        int c = col[e];
        float dr = __ldg(&g_deg[r]);
        float dc = __ldg(&g_deg[c]);
        float ir = (dr > 0.0f) ? rsqrtf(dr) : 0.0f;
        float ic = (dc > 0.0f) ? rsqrtf(dc) : 0.0f;
        float w = -ir * ew[e] * ic;
        int slot = atomicAdd(&g_pos[r], 1);
        g_ecsr[slot] = make_float2(__int_as_float(c), w);
    }
}

// ---------------------------------------------------------------------------
// Row-centric fp16-gather propagation: 8 threads per node, each owns 8
// channels (one uint4 = 16B of fp16). Gather traffic halved vs fp32.
// Accumulation in fp32; result stored fp16.
// ---------------------------------------------------------------------------
__device__ __forceinline__ void prop_accum_edge(float acc[8], float w, uint4 v) {
    const half2* h = (const half2*)&v;
#pragma unroll
    for (int k = 0; k < 4; k++) {
        float2 f = __half22float2(h[k]);
        acc[2 * k + 0] = fmaf(w, f.x, acc[2 * k + 0]);
        acc[2 * k + 1] = fmaf(w, f.y, acc[2 * k + 1]);
    }
}

__device__ __forceinline__ void prop_impl_h(const uint4* __restrict__ src,
                                            uint4* __restrict__ dst,
                                            int gid) {
    int n = gid >> 3;
    int j = gid & 7;
    if (n >= NN) return;

    int s = __ldg(&g_rowstart[n]);
    int e = __ldg(&g_rowstart[n + 1]);

    float acc[8];
#pragma unroll
    for (int k = 0; k < 8; k++) acc[k] = 0.0f;

    int i = s;
    for (; i + 3 < e; i += 4) {
        float2 p[4];
        uint4 v[4];
#pragma unroll
        for (int u = 0; u < 4; u++) p[u] = __ldg(&g_ecsr[i + u]);
#pragma unroll
        for (int u = 0; u < 4; u++)
            v[u] = __ldg(&src[__float_as_int(p[u].x) * 8 + j]);
#pragma unroll
        for (int u = 0; u < 4; u++) prop_accum_edge(acc, p[u].y, v[u]);
    }
    for (; i < e; i++) {
        float2 p = __ldg(&g_ecsr[i]);
        uint4 v = __ldg(&src[__float_as_int(p.x) * 8 + j]);
        prop_accum_edge(acc, p.y, v);
    }

    half2 h0 = __floats2half2_rn(acc[0], acc[1]);
    half2 h1 = __floats2half2_rn(acc[2], acc[3]);
    half2 h2 = __floats2half2_rn(acc[4], acc[5]);
    half2 h3 = __floats2half2_rn(acc[6], acc[7]);
    uint4 o;
    o.x = *(unsigned*)&h0; o.y = *(unsigned*)&h1;
    o.z = *(unsigned*)&h2; o.w = *(unsigned*)&h3;
    dst[n * 8 + j] = o;
}

__global__ void __launch_bounds__(256) prop1_kernel() {
    int gid = blockIdx.x * blockDim.x + threadIdx.x;
    prop_impl_h((const uint4*)g_xh, (uint4*)g_T1h, gid);   // symbols bound in device code
}

__global__ void __launch_bounds__(256) prop2_kernel() {
    int gid = blockIdx.x * blockDim.x + threadIdx.x;
    prop_impl_h((const uint4*)g_T1h, (uint4*)g_P2h, gid);
}

// ---------------------------------------------------------------------------
// Epilogue: out = relu( x@(W0-W2) + T1@W1 + P2@(2*W2) + b )
// x read fp32 (exact); T1/P2 read fp16. FFMA2 accumulators.
// 2 nodes x 16 outputs per thread.
// ---------------------------------------------------------------------------
__global__ void __launch_bounds__(256) epi_kernel(const float* __restrict__ x,
                                                  const float* __restrict__ W,
                                                  const float* __restrict__ b,
                                                  float* __restrict__ out) {
    __shared__ float ws[192 * 64];  // [W0-W2 ; W1 ; 2*W2], each [64][64]

    int tid = threadIdx.x;
    for (int i = tid; i < 4096; i += 256) {
        float w0 = W[i];
        float w1 = W[4096 + i];
        float w2 = W[8192 + i];
        ws[i]        = w0 - w2;
        ws[4096 + i] = w1;
        ws[8192 + i] = 2.0f * w2;
    }
    __syncthreads();

    int np = tid >> 2;           // 0..63 -> node pair
    int og = tid & 3;            // output group: 16 outputs
    int n0 = blockIdx.x * 128 + np * 2;
    int n1 = n0 + 1;
    if (n0 >= NN) return;
    bool has1 = (n1 < NN);

    unsigned long long acc0[8], acc1[8];   // 16 outputs as 8 f32x2 each
#pragma unroll
    for (int o = 0; o < 8; o++) { acc0[o] = 0ULL; acc1[o] = 0ULL; }

    const float4* a0x = (const float4*)(x + (long long)n0 * CC);
    const float4* a1x = (const float4*)(x + (long long)n1 * CC);

#pragma unroll
    for (int part = 0; part < 3; part++) {
        const uint2* h0p = (part == 1) ? (const uint2*)(g_T1h + n0 * CC)
                                       : (const uint2*)(g_P2h + n0 * CC);
        const uint2* h1p = (part == 1) ? (const uint2*)(g_T1h + n1 * CC)
                                       : (const uint2*)(g_P2h + n1 * CC);
        const float* wsp = ws + part * 4096;
        for (int c4 = 0; c4 < 16; c4++) {
            float av0[4], av1[4];
            if (part == 0) {
                float4 a0 = __ldg(&a0x[c4]);
                av0[0] = a0.x; av0[1] = a0.y; av0[2] = a0.z; av0[3] = a0.w;
                if (has1) {
                    float4 a1 = __ldg(&a1x[c4]);
                    av1[0] = a1.x; av1[1] = a1.y; av1[2] = a1.z; av1[3] = a1.w;
                } else {
                    av1[0] = av1[1] = av1[2] = av1[3] = 0.0f;
                }
            } else {
                uint2 h0 = __ldg(&h0p[c4]);
                float2 f0 = __half22float2(*(const half2*)&h0.x);
                float2 f1 = __half22float2(*(const half2*)&h0.y);
                av0[0] = f0.x; av0[1] = f0.y; av0[2] = f1.x; av0[3] = f1.y;
                if (has1) {
                    uint2 h1 = __ldg(&h1p[c4]);
                    float2 g0 = __half22float2(*(const half2*)&h1.x);
                    float2 g1 = __half22float2(*(const half2*)&h1.y);
                    av1[0] = g0.x; av1[1] = g0.y; av1[2] = g1.x; av1[3] = g1.y;
                } else {
                    av1[0] = av1[1] = av1[2] = av1[3] = 0.0f;
                }
            }
#pragma unroll
            for (int t = 0; t < 4; t++) {
                unsigned long long pa0, pa1;
                PACK2(pa0, av0[t], av0[t]);
                PACK2(pa1, av1[t], av1[t]);
                const ulonglong2* wp =
                    (const ulonglong2*)(wsp + (c4 * 4 + t) * 64 + og * 16);
#pragma unroll
                for (int q = 0; q < 4; q++) {
                    ulonglong2 wv = wp[q];
                    FMA2(acc0[q * 2 + 0], pa0, wv.x);
                    FMA2(acc0[q * 2 + 1], pa0, wv.y);
                    FMA2(acc1[q * 2 + 0], pa1, wv.x);
                    FMA2(acc1[q * 2 + 1], pa1, wv.y);
                }
            }
        }
    }

    int jbase = og * 16;
    float4* outp0 = (float4*)(out + (long long)n0 * CC + jbase);
#pragma unroll
    for (int q = 0; q < 4; q++) {
        float lo0, hi0, lo1, hi1;
        UNPACK2(lo0, hi0, acc0[q * 2 + 0]);
        UNPACK2(lo1, hi1, acc0[q * 2 + 1]);
        float4 r;
        r.x = fmaxf(lo0 + __ldg(&b[jbase + q * 4 + 0]), 0.0f);
        r.y = fmaxf(hi0 + __ldg(&b[jbase + q * 4 + 1]), 0.0f);
        r.z = fmaxf(lo1 + __ldg(&b[jbase + q * 4 + 2]), 0.0f);
        r.w = fmaxf(hi1 + __ldg(&b[jbase + q * 4 + 3]), 0.0f);
        outp0[q] = r;
    }
    if (has1) {
        float4* outp1 = (float4*)(out + (long long)n1 * CC + jbase);
#pragma unroll
        for (int q = 0; q < 4; q++) {
            float lo0, hi0, lo1, hi1;
            UNPACK2(lo0, hi0, acc1[q * 2 + 0]);
            UNPACK2(lo1, hi1, acc1[q * 2 + 1]);
            float4 r;
            r.x = fmaxf(lo0 + __ldg(&b[jbase + q * 4 + 0]), 0.0f);
            r.y = fmaxf(hi0 + __ldg(&b[jbase + q * 4 + 1]), 0.0f);
            r.z = fmaxf(lo1 + __ldg(&b[jbase + q * 4 + 2]), 0.0f);
            r.w = fmaxf(hi1 + __ldg(&b[jbase + q * 4 + 3]), 0.0f);
            outp1[q] = r;
        }
    }
}

// ---------------------------------------------------------------------------
// Launch
// ---------------------------------------------------------------------------
extern "C" void kernel_launch(void* const* d_in, const int* in_sizes, int n_in,
                              void* d_out, int out_size) {
    const float* x  = (const float*)d_in[0];   // [N, 64]
    const int*   ei = (const int*)d_in[1];     // [2, E]
    const float* ew = (const float*)d_in[2];   // [E]
    const float* W  = (const float*)d_in[3];   // [3, 64, 64]
    const float* b  = (const float*)d_in[4];   // [64]
    float* out = (float*)d_out;                // [N, 64]

    const int E = in_sizes[2];                 // 800000
    const int* row = ei;
    const int* col = ei + E;

    const int egrid = (NE + 255) / 256;

    zero_convert_kernel<<<1024, 256>>>((const float4*)x);
    deg_kernel<<<egrid, 256>>>(row, ew);
    scan1_kernel<<<NBLK, 256>>>();
    scan2_kernel<<<NBLK, 256>>>();
    scatter_kernel<<<egrid, 256>>>(row, col, ew);

    const int pgrid = (NN * 8 + 255) / 256;
    prop1_kernel<<<pgrid, 256>>>();
    prop2_kernel<<<pgrid, 256>>>();

    epi_kernel<<<(NN + 127) / 128, 256>>>(x, W, b, out);
    (void)E; (void)n_in; (void)out_size;
}